// round 1
// baseline (speedup 1.0000x reference)
#include <cuda_runtime.h>

#define NQ   14
#define NS   (1 << NQ)            // 16384 amplitudes
#define NTH  1024                 // threads per CTA (one CTA per batch element)
#define BATCH 512
#define PAD_SLOTS (NS + (NS >> 5))  // +1 float pad per 32 -> bank-conflict relief

__device__ __forceinline__ int slot(int j) { return j + (j >> 5); }

// One "mix" = [c, -i s; -i s, c] acting on (x, y) complex pair.
// Covers both Rx (pair differing in one bit) and IsingXX (s00<->s11, s01<->s10).
__device__ __forceinline__ void mixg(float& xr, float& xi, float& yr, float& yi,
                                     float c, float s) {
    float nxr = fmaf(c, xr,  s * yi);
    float nxi = fmaf(c, xi, -s * yr);
    float nyr = fmaf(c, yr,  s * xi);
    float nyi = fmaf(c, yi, -s * xr);
    xr = nxr; xi = nxi; yr = nyr; yi = nyi;
}

// amp *= exp(i*phi) given (cq, sp) = (cos phi, sin phi)
__device__ __forceinline__ void rotp(float& r, float& m, float cq, float sp) {
    float nr = fmaf(r, cq, -m * sp);
    float nm = fmaf(m, cq,  r * sp);
    r = nr; m = nm;
}

// Compose the 14 MCX permutations (each an involution) and accumulate
// signed probability into per-wire accumulators.
__device__ __forceinline__ void accum_amp(int i, float r, float m, float* acc) {
    unsigned x = (unsigned)i;
#pragma unroll
    for (int w = 0; w < NQ; w++) {
        const int p1 = NQ - 1 - w;
        const int p2 = NQ - 1 - ((w + 1) % NQ);
        const int pt = NQ - 1 - ((w + 2) % NQ);
        unsigned b1 = (x >> p1) & 1u;
        unsigned b2 = (x >> p2) & 1u;
        x ^= ((b1 & (b2 ^ 1u)) << pt);
    }
    float pr = fmaf(r, r, m * m);
#pragma unroll
    for (int w = 0; w < NQ; w++) {
        unsigned bit = (x >> (NQ - 1 - w)) & 1u;
        acc[w] += __uint_as_float(__float_as_uint(pr) ^ (bit << 31));
    }
}

// MODE 0: plain XX pass.
// MODE 1: XX pass + fused Rz diagonal (must be the LAST layer-1 pass; HP=1,LP=0).
// MODE 2: XX pass + fused Rx (layer 3) on both wires of the pair.
// MODE 3: MODE 2 + fused epilogue (perm + prob + sign-reduce), no store.
template <int HP, int LP, int MODE>
__device__ __forceinline__ void quad_pass(float* RE, float* IM,
                                          float c, float s,
                                          float cA, float sA,   // Rx on HP-bit wire
                                          float cB, float sB,   // Rx on LP-bit wire
                                          const float* thz, float base,
                                          float* acc) {
    const int tid = threadIdx.x;
#pragma unroll
    for (int k = 0; k < 4; k++) {
        int g  = k * NTH + tid;                                   // quad id 0..4095
        int x  = ((g >> LP) << (LP + 1)) | (g & ((1 << LP) - 1)); // insert 0 at LP
        int i0 = ((x >> HP) << (HP + 1)) | (x & ((1 << HP) - 1)); // insert 0 at HP
        int iB = i0 | (1 << LP);
        int iA = i0 | (1 << HP);
        int iC = iA | (1 << LP);
        int s0 = slot(i0), sb = slot(iB), sa = slot(iA), sc = slot(iC);

        float r0 = RE[s0], m0 = IM[s0];
        float r1 = RE[sb], m1 = IM[sb];
        float r2 = RE[sa], m2 = IM[sa];
        float r3 = RE[sc], m3 = IM[sc];

        // IsingXX: (s00,s11) and (s01,s10)
        mixg(r0, m0, r3, m3, c, s);
        mixg(r1, m1, r2, m2, c, s);

        if (MODE == 2 || MODE == 3) {
            // Rx layer 3 on the HP wire: pairs differ in HP bit
            mixg(r0, m0, r2, m2, cA, sA);
            mixg(r1, m1, r3, m3, cA, sA);
            // Rx layer 3 on the LP wire
            mixg(r0, m0, r1, m1, cB, sB);
            mixg(r2, m2, r3, m3, cB, sB);
        }

        if (MODE == 1) {
            // Fused Rz diagonal: phi(j) = base + sum_{set bits} theta[wire]
            float phi0 = base;
#pragma unroll
            for (int bb = 2; bb < NQ; bb++)
                phi0 += ((i0 >> bb) & 1) ? thz[NQ - 1 - bb] : 0.0f;
            float tA = thz[NQ - 1 - HP];
            float tB = thz[NQ - 1 - LP];
            float sp, cq;
            sincosf(phi0,           &sp, &cq); rotp(r0, m0, cq, sp);
            sincosf(phi0 + tB,      &sp, &cq); rotp(r1, m1, cq, sp);
            sincosf(phi0 + tA,      &sp, &cq); rotp(r2, m2, cq, sp);
            sincosf(phi0 + tA + tB, &sp, &cq); rotp(r3, m3, cq, sp);
        }

        if (MODE == 3) {
            accum_amp(i0, r0, m0, acc);
            accum_amp(iB, r1, m1, acc);
            accum_amp(iA, r2, m2, acc);
            accum_amp(iC, r3, m3, acc);
        } else {
            RE[s0] = r0; IM[s0] = m0;
            RE[sb] = r1; IM[sb] = m1;
            RE[sa] = r2; IM[sa] = m2;
            RE[sc] = r3; IM[sc] = m3;
        }
    }
    __syncthreads();
}

__global__ void __launch_bounds__(NTH, 1)
quantum_kernel(const float* __restrict__ cp, const float* __restrict__ p,
               float* __restrict__ out) {
    extern __shared__ float sm[];
    float* RE = sm;
    float* IM = sm + PAD_SLOTS;

    __shared__ float c1[NQ], s1[NQ];       // Rx layer 1 half-angle cos/sin
    __shared__ float c3[NQ], s3[NQ];       // Rx layer 3
    __shared__ float thz[NQ];              // Rz thetas
    __shared__ float cxa[7], sxa[7];       // XX layer 1
    __shared__ float cxb[7], sxb[7];       // XX layer 2
    __shared__ float thz_base;
    __shared__ float red[32][16];          // warp-reduction scratch

    const int tid = threadIdx.x;
    const int b   = blockIdx.x;

    // ---- angle setup ----
    if (tid < NQ) {
        float a1 = 0.5f * p[(b * 3 + 0) * NQ + tid];
        sincosf(a1, &s1[tid], &c1[tid]);
        float a3 = 0.5f * p[(b * 3 + 2) * NQ + tid];
        sincosf(a3, &s3[tid], &c3[tid]);
        thz[tid] = p[(b * 3 + 1) * NQ + tid];
    } else if (tid >= 32 && tid < 39) {
        int ws = tid - 32;
        sincosf(0.5f * cp[b * NQ + ws], &sxa[ws], &cxa[ws]);
    } else if (tid >= 64 && tid < 71) {
        int ws = tid - 64;
        sincosf(0.5f * cp[b * NQ + 7 + ws], &sxb[ws], &cxb[ws]);
    }
    __syncthreads();

    if (tid == 0) {
        float sum = 0.0f;
#pragma unroll
        for (int w = 0; w < NQ; w++) sum += thz[w];
        thz_base = -0.5f * sum;   // published by the sync after the init pass
    }

    // ---- init pass: product state = Rx layer 1 applied to |0..0> ----
    {
        float plo = 1.0f;
#pragma unroll
        for (int bb = 0; bb < 10; bb++)
            plo *= ((tid >> bb) & 1) ? s1[NQ - 1 - bb] : c1[NQ - 1 - bb];
        int pc_lo = __popc(tid);
#pragma unroll
        for (int k = 0; k < 16; k++) {
            float P = plo;
#pragma unroll
            for (int bb = 10; bb < NQ; bb++)
                P *= ((k >> (bb - 10)) & 1) ? s1[NQ - 1 - bb] : c1[NQ - 1 - bb];
            int pc = (pc_lo + __popc(k)) & 3;        // (-i)^popc phase
            float re = (pc & 1) ? 0.0f : ((pc & 2) ? -P : P);
            float im = (pc & 1) ? ((pc & 2) ? P : -P) : 0.0f;
            int j = k * NTH + tid;
            RE[slot(j)] = re;
            IM[slot(j)] = im;
        }
    }
    __syncthreads();

    float acc[NQ];
#pragma unroll
    for (int w = 0; w < NQ; w++) acc[w] = 0.0f;

    float base = thz_base;

    // ---- layer 1 XX: wires (2ws, 2ws+1) -> bit positions (13-2ws, 12-2ws) ----
    quad_pass<13, 12, 0>(RE, IM, cxa[0], sxa[0], 0, 0, 0, 0, thz, 0, acc);
    quad_pass<11, 10, 0>(RE, IM, cxa[1], sxa[1], 0, 0, 0, 0, thz, 0, acc);
    quad_pass< 9,  8, 0>(RE, IM, cxa[2], sxa[2], 0, 0, 0, 0, thz, 0, acc);
    quad_pass< 7,  6, 0>(RE, IM, cxa[3], sxa[3], 0, 0, 0, 0, thz, 0, acc);
    quad_pass< 5,  4, 0>(RE, IM, cxa[4], sxa[4], 0, 0, 0, 0, thz, 0, acc);
    quad_pass< 3,  2, 0>(RE, IM, cxa[5], sxa[5], 0, 0, 0, 0, thz, 0, acc);
    // last layer-1 pass carries the fused Rz diagonal
    quad_pass< 1,  0, 1>(RE, IM, cxa[6], sxa[6], 0, 0, 0, 0, thz, base, acc);

    // ---- layer 2 XX: wires (2ws+1, 2ws+2) -> positions (12-2ws, 11-2ws),
    //      each pass also applies Rx layer 3 on its two wires ----
    quad_pass<12, 11, 2>(RE, IM, cxb[0], sxb[0], c3[ 1], s3[ 1], c3[ 2], s3[ 2], thz, 0, acc);
    quad_pass<10,  9, 2>(RE, IM, cxb[1], sxb[1], c3[ 3], s3[ 3], c3[ 4], s3[ 4], thz, 0, acc);
    quad_pass< 8,  7, 2>(RE, IM, cxb[2], sxb[2], c3[ 5], s3[ 5], c3[ 6], s3[ 6], thz, 0, acc);
    quad_pass< 6,  5, 2>(RE, IM, cxb[3], sxb[3], c3[ 7], s3[ 7], c3[ 8], s3[ 8], thz, 0, acc);
    quad_pass< 4,  3, 2>(RE, IM, cxb[4], sxb[4], c3[ 9], s3[ 9], c3[10], s3[10], thz, 0, acc);
    quad_pass< 2,  1, 2>(RE, IM, cxb[5], sxb[5], c3[11], s3[11], c3[12], s3[12], thz, 0, acc);
    // wrap pair: wires (13, 0) -> positions (0, 13). HP=13 is wire 0, LP=0 is wire 13.
    // Fused epilogue: MCX perm composition + probs + Z-sign reduction.
    quad_pass<13,  0, 3>(RE, IM, cxb[6], sxb[6], c3[ 0], s3[ 0], c3[13], s3[13], thz, 0, acc);

    // ---- reduction: warp shuffle + cross-warp via shared ----
#pragma unroll
    for (int w = 0; w < NQ; w++) {
        float v = acc[w];
#pragma unroll
        for (int o = 16; o; o >>= 1) v += __shfl_xor_sync(0xffffffffu, v, o);
        if ((tid & 31) == 0) red[tid >> 5][w] = v;
    }
    __syncthreads();
    if (tid < NQ) {
        float v = 0.0f;
#pragma unroll
        for (int wp = 0; wp < 32; wp++) v += red[wp][tid];
        out[b * NQ + tid] = v;
    }
}

extern "C" void kernel_launch(void* const* d_in, const int* in_sizes, int n_in,
                              void* d_out, int out_size) {
    const float* cp = (const float*)d_in[0];   // (512, 14)
    const float* p  = (const float*)d_in[1];   // (512, 3, 14)
    float* out      = (float*)d_out;           // (512, 14)

    size_t smem = (size_t)PAD_SLOTS * 2 * sizeof(float);  // 135168 bytes
    cudaFuncSetAttribute(quantum_kernel,
                         cudaFuncAttributeMaxDynamicSharedMemorySize, (int)smem);
    quantum_kernel<<<BATCH, NTH, smem>>>(cp, p, out);
}

// round 2
// speedup vs baseline: 1.9192x; 1.9192x over previous
#include <cuda_runtime.h>

#define NQ    14
#define NS    16384
#define NTH   1024
#define BATCH 512
#define PAD_SLOTS (NS + (NS >> 5))   // 16896

// ---------------- MCX permutation table (built once per launch) -------------
__device__ unsigned short d_permtab[NS];

__global__ void build_perm_kernel() {
    int i = blockIdx.x * blockDim.x + threadIdx.x;
    unsigned x = (unsigned)i;
#pragma unroll
    for (int w = 0; w < NQ; w++) {
        const int p1 = NQ - 1 - w;
        const int p2 = NQ - 1 - ((w + 1) % NQ);
        const int pt = NQ - 1 - ((w + 2) % NQ);
        unsigned b1 = (x >> p1) & 1u;
        unsigned b2 = (x >> p2) & 1u;
        x ^= ((b1 & (b2 ^ 1u)) << pt);
    }
    d_permtab[i] = (unsigned short)x;
}

// ---------------- register-space gate helpers -------------------------------
__device__ __forceinline__ void mixg(float& xr, float& xi, float& yr, float& yi,
                                     float c, float s) {
    float nxr = fmaf(c, xr,  s * yi);
    float nxi = fmaf(c, xi, -s * yr);
    float nyr = fmaf(c, yr,  s * xi);
    float nyi = fmaf(c, yi, -s * xr);
    xr = nxr; xi = nxi; yr = nyr; yi = nyi;
}

// IsingXX on resident-bit masks MA, MB (register space)
template <int MA, int MB>
__device__ __forceinline__ void xx16(float (&vr)[16], float (&vi)[16],
                                     float c, float s) {
    const int M = MA | MB;
#pragma unroll
    for (int t = 0; t < 16; t++) {
        if (t & M) continue;
        mixg(vr[t],      vi[t],      vr[t ^ M],  vi[t ^ M],  c, s);  // 00<->11
        mixg(vr[t | MA], vi[t | MA], vr[t | MB], vi[t | MB], c, s);  // 10<->01
    }
}

// Rx on resident-bit mask M
template <int M>
__device__ __forceinline__ void rx16(float (&vr)[16], float (&vi)[16],
                                     float c, float s) {
#pragma unroll
    for (int t = 0; t < 16; t++) {
        if (t & M) continue;
        mixg(vr[t], vi[t], vr[t | M], vi[t | M], c, s);
    }
}

// Rz on resident-bit mask M, global phase dropped: bit=1 half gets e^{+i theta}
template <int M>
__device__ __forceinline__ void rz16(float (&vr)[16], float (&vi)[16],
                                     float cz, float sz) {
#pragma unroll
    for (int t = 0; t < 16; t++) {
        if (!(t & M)) continue;
        float nr = fmaf(vr[t], cz, -vi[t] * sz);
        float ni = fmaf(vi[t], cz,  vr[t] * sz);
        vr[t] = nr; vi[t] = ni;
    }
}

// ---------------- main kernel ------------------------------------------------
__global__ void __launch_bounds__(NTH, 1)
quantum_kernel(const float* __restrict__ cp, const float* __restrict__ p,
               float* __restrict__ out) {
    extern __shared__ float sm[];
    float* RE = sm;
    float* IM = sm + PAD_SLOTS;

    __shared__ float c1[NQ], s1[NQ];     // Rx layer-1 half-angle
    __shared__ float czf[NQ], szf[NQ];   // Rz FULL angle (global phase dropped)
    __shared__ float c3[NQ], s3[NQ];     // Rx layer-3 half-angle
    __shared__ float cxv[NQ], sxv[NQ];   // XX half-angle: [0..6]=layer a, [7..13]=layer b
    __shared__ float red[32][NQ];

    const int tid = threadIdx.x;
    const int b   = blockIdx.x;

    if (tid < NQ) {
        sincosf(0.5f * p[b * 3 * NQ + tid], &s1[tid], &c1[tid]);
    } else if (tid < 2 * NQ) {
        int w = tid - NQ;
        sincosf(p[b * 3 * NQ + NQ + w], &szf[w], &czf[w]);
    } else if (tid < 3 * NQ) {
        int w = tid - 2 * NQ;
        sincosf(0.5f * p[b * 3 * NQ + 2 * NQ + w], &s3[w], &c3[w]);
    } else if (tid < 4 * NQ) {
        int w = tid - 3 * NQ;
        sincosf(0.5f * cp[b * NQ + w], &sxv[w], &cxv[w]);
    }
    __syncthreads();

    float vr[16], vi[16];

    // ================= P1 : resident bits {13,12,11,10} = qubits {0,1,2,3} ==
    // init product state (Rx layer 1 on |0>) directly in registers
    {
        float pl = 1.0f;
#pragma unroll
        for (int bb = 0; bb < 10; bb++)
            pl *= ((tid >> bb) & 1) ? s1[13 - bb] : c1[13 - bb];
        int pc0 = __popc(tid);
#pragma unroll
        for (int t = 0; t < 16; t++) {
            float P = pl;
#pragma unroll
            for (int k = 0; k < 4; k++)
                P *= ((t >> k) & 1) ? s1[3 - k] : c1[3 - k];
            int pc = (pc0 + __popc(t)) & 3;        // (-i)^popc
            vr[t] = (pc & 1) ? 0.0f : ((pc & 2) ? -P : P);
            vi[t] = (pc & 1) ? ((pc == 1) ? -P : P) : 0.0f;
        }
    }
    xx16<8, 4>(vr, vi, cxv[0], sxv[0]);            // XXa(q0,q1)
    xx16<2, 1>(vr, vi, cxv[1], sxv[1]);            // XXa(q2,q3)
    rz16<8>(vr, vi, czf[0], szf[0]);
    rz16<4>(vr, vi, czf[1], szf[1]);
    rz16<2>(vr, vi, czf[2], szf[2]);
    rz16<1>(vr, vi, czf[3], szf[3]);
    xx16<4, 2>(vr, vi, cxv[7], sxv[7]);            // XXb(q1,q2)
    rx16<4>(vr, vi, c3[1], s3[1]);
    rx16<2>(vr, vi, c3[2], s3[2]);
    {
        int a = tid + (tid >> 5);
#pragma unroll
        for (int t = 0; t < 16; t++) {
            int off = a + t * 1056;                // slot(t<<10)
            RE[off] = vr[t]; IM[off] = vi[t];
        }
    }
    __syncthreads();

    // ================= P2 : resident {9,8,7,6} = qubits {4,5,6,7} ===========
    {
        int base = (tid & 63) | ((tid >> 6) << 10);
        int a = base + (base >> 5);
#pragma unroll
        for (int t = 0; t < 16; t++) {
            int off = a + t * 66;                  // slot(t<<6)
            vr[t] = RE[off]; vi[t] = IM[off];
        }
        xx16<8, 4>(vr, vi, cxv[2], sxv[2]);        // XXa(q4,q5)
        xx16<2, 1>(vr, vi, cxv[3], sxv[3]);        // XXa(q6,q7)
        rz16<8>(vr, vi, czf[4], szf[4]);
        rz16<4>(vr, vi, czf[5], szf[5]);
        rz16<2>(vr, vi, czf[6], szf[6]);
        rz16<1>(vr, vi, czf[7], szf[7]);
        xx16<4, 2>(vr, vi, cxv[9], sxv[9]);        // XXb(q5,q6)
        rx16<4>(vr, vi, c3[5], s3[5]);
        rx16<2>(vr, vi, c3[6], s3[6]);
#pragma unroll
        for (int t = 0; t < 16; t++) {
            int off = a + t * 66;
            RE[off] = vr[t]; IM[off] = vi[t];
        }
    }
    __syncthreads();

    // ================= P3 : resident {5,4,3,2} = qubits {8,9,10,11} =========
    {
        int base = (tid & 3) | (((tid >> 5) & 1) << 6) |
                   (((tid >> 2) & 7) << 7) | (((tid >> 6) & 15) << 10);
        int a = base + (base >> 5);
#pragma unroll
        for (int t = 0; t < 16; t++) {
            int off = a + t * 4 + (t >> 3);        // slot(t<<2)
            vr[t] = RE[off]; vi[t] = IM[off];
        }
        xx16<8, 4>(vr, vi, cxv[4], sxv[4]);        // XXa(q8,q9)
        xx16<2, 1>(vr, vi, cxv[5], sxv[5]);        // XXa(q10,q11)
        rz16<8>(vr, vi, czf[8],  szf[8]);
        rz16<4>(vr, vi, czf[9],  szf[9]);
        rz16<2>(vr, vi, czf[10], szf[10]);
        rz16<1>(vr, vi, czf[11], szf[11]);
        xx16<4, 2>(vr, vi, cxv[11], sxv[11]);      // XXb(q9,q10)
        rx16<4>(vr, vi, c3[9],  s3[9]);
        rx16<2>(vr, vi, c3[10], s3[10]);
#pragma unroll
        for (int t = 0; t < 16; t++) {
            int off = a + t * 4 + (t >> 3);
            RE[off] = vr[t]; IM[off] = vi[t];
        }
    }
    __syncthreads();

    // ================= P4 : resident {10,9,6,5} = qubits {3,4,7,8} ==========
    {
        int base = (tid & 31) | (((tid >> 5) & 3) << 7) | (((tid >> 7) & 7) << 11);
        int a = base + (base >> 5);
#pragma unroll
        for (int t = 0; t < 16; t++) {
            int off = a + ((t >> 3) & 1) * 1056 + ((t >> 2) & 1) * 528
                        + ((t >> 1) & 1) * 66   + (t & 1) * 33;
            vr[t] = RE[off]; vi[t] = IM[off];
        }
        xx16<8, 4>(vr, vi, cxv[8],  sxv[8]);       // XXb(q3,q4)
        xx16<2, 1>(vr, vi, cxv[10], sxv[10]);      // XXb(q7,q8)
        rx16<8>(vr, vi, c3[3], s3[3]);
        rx16<4>(vr, vi, c3[4], s3[4]);
        rx16<2>(vr, vi, c3[7], s3[7]);
        rx16<1>(vr, vi, c3[8], s3[8]);
#pragma unroll
        for (int t = 0; t < 16; t++) {
            int off = a + ((t >> 3) & 1) * 1056 + ((t >> 2) & 1) * 528
                        + ((t >> 1) & 1) * 66   + (t & 1) * 33;
            RE[off] = vr[t]; IM[off] = vi[t];
        }
    }
    __syncthreads();

    // ================= P5 : resident {13,2,1,0} = qubits {0,11,12,13} =======
    float acc[NQ], T = 0.0f;
#pragma unroll
    for (int w = 0; w < NQ; w++) acc[w] = 0.0f;
    {
        int base = ((tid & 3) << 3) | (((tid >> 2) & 7) << 5) |
                   (((tid >> 5) & 31) << 8);
        int a = base + (base >> 5);
#pragma unroll
        for (int t = 0; t < 16; t++) {
            int off = a + ((t >> 3) & 1) * 8448 + (t & 7);
            vr[t] = RE[off]; vi[t] = IM[off];
        }
        xx16<2, 1>(vr, vi, cxv[6], sxv[6]);        // XXa(q12,q13)
        rz16<2>(vr, vi, czf[12], szf[12]);
        rz16<1>(vr, vi, czf[13], szf[13]);
        xx16<4, 2>(vr, vi, cxv[12], sxv[12]);      // XXb(q11,q12)
        xx16<1, 8>(vr, vi, cxv[13], sxv[13]);      // XXb(q13,q0)
        rx16<8>(vr, vi, c3[0],  s3[0]);
        rx16<4>(vr, vi, c3[11], s3[11]);
        rx16<2>(vr, vi, c3[12], s3[12]);
        rx16<1>(vr, vi, c3[13], s3[13]);

        // fused epilogue: permuted index from table, probability, signed sums
#pragma unroll
        for (int t = 0; t < 16; t++) {
            int j = base | (((t >> 3) & 1) << 13) | (t & 7);
            unsigned x = (unsigned)d_permtab[j];
            float pr = fmaf(vr[t], vr[t], vi[t] * vi[t]);
            T += pr;
#pragma unroll
            for (int w = 0; w < NQ; w++)
                acc[w] += ((x >> (NQ - 1 - w)) & 1u) ? pr : 0.0f;
        }
    }

    // out_w = sum pr*(1-2*bit) = T - 2*acc_w ; reduce across the CTA
#pragma unroll
    for (int w = 0; w < NQ; w++) {
        float v = fmaf(-2.0f, acc[w], T);
#pragma unroll
        for (int o = 16; o; o >>= 1) v += __shfl_xor_sync(0xffffffffu, v, o);
        if ((tid & 31) == 0) red[tid >> 5][w] = v;
    }
    __syncthreads();
    if (tid < NQ) {
        float v = 0.0f;
#pragma unroll
        for (int wp = 0; wp < 32; wp++) v += red[wp][tid];
        out[b * NQ + tid] = v;
    }
}

extern "C" void kernel_launch(void* const* d_in, const int* in_sizes, int n_in,
                              void* d_out, int out_size) {
    const float* cp = (const float*)d_in[0];   // (512, 14)
    const float* p  = (const float*)d_in[1];   // (512, 3, 14)
    float* out      = (float*)d_out;           // (512, 14)

    build_perm_kernel<<<NS / NTH, NTH>>>();

    size_t smem = (size_t)PAD_SLOTS * 2 * sizeof(float);  // 135168 bytes
    cudaFuncSetAttribute(quantum_kernel,
                         cudaFuncAttributeMaxDynamicSharedMemorySize, (int)smem);
    quantum_kernel<<<BATCH, NTH, smem>>>(cp, p, out);
}

// round 4
// speedup vs baseline: 2.4072x; 1.2543x over previous
#include <cuda_runtime.h>

#define NQ    14
#define NS    16384
#define NTH   512
#define BATCH 512
#define PAD_SLOTS (NS + (NS >> 5))   // 16896

typedef unsigned long long u64;

// ---------------- INVERSE MCX permutation table -----------------------------
// Forward perm (reference order): j_new = p13(...p1(p0(i))...)
// Epilogue gathers, so we need the inverse: x = p0(p1(...p13(y)...)).
// Build by applying the involutions in REVERSE order.
__device__ unsigned short d_permtab[NS];

__global__ void build_perm_kernel() {
    int i = blockIdx.x * blockDim.x + threadIdx.x;
    unsigned x = (unsigned)i;
#pragma unroll
    for (int w = NQ - 1; w >= 0; w--) {
        const int p1 = NQ - 1 - w;
        const int p2 = NQ - 1 - ((w + 1) % NQ);
        const int pt = NQ - 1 - ((w + 2) % NQ);
        unsigned b1 = (x >> p1) & 1u;
        unsigned b2 = (x >> p2) & 1u;
        x ^= ((b1 & (b2 ^ 1u)) << pt);
    }
    d_permtab[i] = (unsigned short)x;
}

// ---------------- packed f32x2 primitives ------------------------------------
__device__ __forceinline__ u64 mul2(u64 a, u64 b) {
    u64 d; asm("mul.rn.f32x2 %0,%1,%2;" : "=l"(d) : "l"(a), "l"(b)); return d;
}
__device__ __forceinline__ u64 fma2(u64 a, u64 b, u64 c) {
    u64 d; asm("fma.rn.f32x2 %0,%1,%2,%3;" : "=l"(d) : "l"(a), "l"(b), "l"(c)); return d;
}
__device__ __forceinline__ u64 pk2(float lo, float hi) {
    u64 d; asm("mov.b64 %0,{%1,%2};" : "=l"(d) : "f"(lo), "f"(hi)); return d;
}
__device__ __forceinline__ void up2(u64 v, float& lo, float& hi) {
    asm("mov.b64 {%0,%1},%2;" : "=f"(lo), "=f"(hi) : "l"(v));
}

struct G { u64 C, S, Sn; };
__device__ __forceinline__ G mkg(float c, float s) {
    G g; g.C = pk2(c, c); g.S = pk2(s, s); g.Sn = pk2(-s, -s); return g;
}

// mix on packed pair: nXr = C*Xr + S*Yi ; nXi = C*Xi - S*Yr ; symmetric for Y
__device__ __forceinline__ void mix2(u64& Xr, u64& Xi, u64& Yr, u64& Yi, const G& g) {
    u64 xr = Xr, xi = Xi, yr = Yr, yi = Yi;
    Xr = fma2(g.C, xr, mul2(g.S,  yi));
    Xi = fma2(g.C, xi, mul2(g.Sn, yr));
    Yr = fma2(g.C, yr, mul2(g.S,  xi));
    Yi = fma2(g.C, yi, mul2(g.Sn, xr));
}

template <int MA, int MB>
__device__ __forceinline__ void xx(u64* Ar, u64* Ai, const G& g) {
    const int M = MA | MB;
#pragma unroll
    for (int t = 0; t < 16; t++) {
        if (t & M) continue;
        mix2(Ar[t],      Ai[t],      Ar[t ^ M],  Ai[t ^ M],  g);  // 00<->11
        mix2(Ar[t | MA], Ai[t | MA], Ar[t | MB], Ai[t | MB], g);  // 10<->01
    }
}
template <int M>
__device__ __forceinline__ void rx(u64* Ar, u64* Ai, const G& g) {
#pragma unroll
    for (int t = 0; t < 16; t++) {
        if (t & M) continue;
        mix2(Ar[t], Ai[t], Ar[t | M], Ai[t | M], g);
    }
}
// Rz (global phase dropped): bit=1 component *= e^{+i theta}
template <int M>
__device__ __forceinline__ void rz(u64* Ar, u64* Ai, const G& g) {
#pragma unroll
    for (int t = 0; t < 16; t++) {
        if (!(t & M)) continue;
        u64 r = Ar[t], i = Ai[t];
        Ar[t] = fma2(g.C, r, mul2(g.Sn, i));
        Ai[t] = fma2(g.C, i, mul2(g.S,  r));
    }
}

// ---------------- main kernel ------------------------------------------------
__global__ void __launch_bounds__(NTH, 1)
quantum_kernel(const float* __restrict__ cp, const float* __restrict__ p,
               float* __restrict__ out) {
    extern __shared__ float sm[];
    float* RE = sm;
    float* IM = sm + PAD_SLOTS;

    __shared__ float c1[NQ], s1[NQ];     // Rx layer-1 half-angle
    __shared__ float czf[NQ], szf[NQ];   // Rz FULL angle
    __shared__ float c3[NQ], s3[NQ];     // Rx layer-3 half-angle
    __shared__ float cxv[NQ], sxv[NQ];   // XX half-angle: [0..6]=a, [7..13]=b
    __shared__ float red[16][NQ];

    const int tid = threadIdx.x;
    const int b   = blockIdx.x;

    if (tid < NQ) {
        sincosf(0.5f * p[b * 3 * NQ + tid], &s1[tid], &c1[tid]);
    } else if (tid < 2 * NQ) {
        int w = tid - NQ;
        sincosf(p[b * 3 * NQ + NQ + w], &szf[w], &czf[w]);
    } else if (tid < 3 * NQ) {
        int w = tid - 2 * NQ;
        sincosf(0.5f * p[b * 3 * NQ + 2 * NQ + w], &s3[w], &c3[w]);
    } else if (tid < 4 * NQ) {
        int w = tid - 3 * NQ;
        sincosf(0.5f * cp[b * NQ + w], &sxv[w], &cxv[w]);
    }
    __syncthreads();

    u64 Ar[16], Ai[16];

    // ====== P1: gate bits {13,12,11,10} = qubits 0-3, pack bit 9 (qubit 4) ===
    // j = (t<<10) | (pk<<9) | tid
    {
        float pl = 1.0f;
#pragma unroll
        for (int bb = 0; bb < 9; bb++)
            pl *= ((tid >> bb) & 1) ? s1[13 - bb] : c1[13 - bb];
        int pc0 = __popc(tid);
        float f9c = c1[4], f9s = s1[4];
#pragma unroll
        for (int t = 0; t < 16; t++) {
            float Pb = pl;
#pragma unroll
            for (int k = 0; k < 4; k++)
                Pb *= ((t >> k) & 1) ? s1[3 - k] : c1[3 - k];
            int pcl = pc0 + __popc(t);
            float P0 = Pb * f9c;   int q0 = pcl & 3;
            float re0 = (q0 & 1) ? 0.0f : ((q0 & 2) ? -P0 : P0);
            float im0 = (q0 & 1) ? ((q0 == 1) ? -P0 : P0) : 0.0f;
            float P1v = Pb * f9s;  int q1 = (pcl + 1) & 3;
            float re1 = (q1 & 1) ? 0.0f : ((q1 & 2) ? -P1v : P1v);
            float im1 = (q1 & 1) ? ((q1 == 1) ? -P1v : P1v) : 0.0f;
            Ar[t] = pk2(re0, re1);
            Ai[t] = pk2(im0, im1);
        }
    }
    { G g = mkg(cxv[0], sxv[0]); xx<8, 4>(Ar, Ai, g); }   // XXa(0,1)
    { G g = mkg(cxv[1], sxv[1]); xx<2, 1>(Ar, Ai, g); }   // XXa(2,3)
    { G g = mkg(czf[0], szf[0]); rz<8>(Ar, Ai, g); }
    { G g = mkg(czf[1], szf[1]); rz<4>(Ar, Ai, g); }
    { G g = mkg(czf[2], szf[2]); rz<2>(Ar, Ai, g); }
    { G g = mkg(czf[3], szf[3]); rz<1>(Ar, Ai, g); }
    { G g = mkg(cxv[7], sxv[7]); xx<4, 2>(Ar, Ai, g); }   // XXb(1,2)
    { G g = mkg(c3[1], s3[1]);   rx<4>(Ar, Ai, g); }
    { G g = mkg(c3[2], s3[2]);   rx<2>(Ar, Ai, g); }
    {
        int a = tid + (tid >> 5);
#pragma unroll
        for (int t = 0; t < 16; t++) {
            int o = a + t * 1056; float lo, hi;
            up2(Ar[t], lo, hi); RE[o] = lo; RE[o + 528] = hi;
            up2(Ai[t], lo, hi); IM[o] = lo; IM[o + 528] = hi;
        }
    }
    __syncthreads();

    // ====== P2: gate bits {9,8,7,6} = qubits 4-7, pack bit 5 (qubit 8) ======
    // j = (tid>>5)<<10 | t<<6 | pk<<5 | (tid&31)
    {
        int a = (tid >> 5) * 1056 + (tid & 31);
#pragma unroll
        for (int t = 0; t < 16; t++) {
            int o = a + t * 66;
            Ar[t] = pk2(RE[o], RE[o + 33]);
            Ai[t] = pk2(IM[o], IM[o + 33]);
        }
        { G g = mkg(cxv[2], sxv[2]); xx<8, 4>(Ar, Ai, g); }   // XXa(4,5)
        { G g = mkg(cxv[3], sxv[3]); xx<2, 1>(Ar, Ai, g); }   // XXa(6,7)
        { G g = mkg(czf[4], szf[4]); rz<8>(Ar, Ai, g); }
        { G g = mkg(czf[5], szf[5]); rz<4>(Ar, Ai, g); }
        { G g = mkg(czf[6], szf[6]); rz<2>(Ar, Ai, g); }
        { G g = mkg(czf[7], szf[7]); rz<1>(Ar, Ai, g); }
        { G g = mkg(cxv[9], sxv[9]); xx<4, 2>(Ar, Ai, g); }   // XXb(5,6)
        { G g = mkg(c3[5], s3[5]);   rx<4>(Ar, Ai, g); }
        { G g = mkg(c3[6], s3[6]);   rx<2>(Ar, Ai, g); }
#pragma unroll
        for (int t = 0; t < 16; t++) {
            int o = a + t * 66; float lo, hi;
            up2(Ar[t], lo, hi); RE[o] = lo; RE[o + 33] = hi;
            up2(Ai[t], lo, hi); IM[o] = lo; IM[o + 33] = hi;
        }
    }
    __syncthreads();

    // ====== P3: gate bits {5,4,3,2} = qubits 8-11, pack bit 6 (qubit 7) =====
    // j = (tid>>2)<<7 | pk<<6 | t<<2 | (tid&3)
    {
        int a = (tid >> 2) * 132 + (tid & 3);
#pragma unroll
        for (int t = 0; t < 16; t++) {
            int o = a + t * 4 + (t >> 3);
            Ar[t] = pk2(RE[o], RE[o + 66]);
            Ai[t] = pk2(IM[o], IM[o + 66]);
        }
        { G g = mkg(cxv[4], sxv[4]);  xx<8, 4>(Ar, Ai, g); }  // XXa(8,9)
        { G g = mkg(cxv[5], sxv[5]);  xx<2, 1>(Ar, Ai, g); }  // XXa(10,11)
        { G g = mkg(czf[8],  szf[8]);  rz<8>(Ar, Ai, g); }
        { G g = mkg(czf[9],  szf[9]);  rz<4>(Ar, Ai, g); }
        { G g = mkg(czf[10], szf[10]); rz<2>(Ar, Ai, g); }
        { G g = mkg(czf[11], szf[11]); rz<1>(Ar, Ai, g); }
        { G g = mkg(cxv[11], sxv[11]); xx<4, 2>(Ar, Ai, g); } // XXb(9,10)
        { G g = mkg(c3[9],  s3[9]);   rx<4>(Ar, Ai, g); }
        { G g = mkg(c3[10], s3[10]);  rx<2>(Ar, Ai, g); }
#pragma unroll
        for (int t = 0; t < 16; t++) {
            int o = a + t * 4 + (t >> 3); float lo, hi;
            up2(Ar[t], lo, hi); RE[o] = lo; RE[o + 66] = hi;
            up2(Ai[t], lo, hi); IM[o] = lo; IM[o + 66] = hi;
        }
    }
    __syncthreads();

    // ====== P4: gate bits {10,9,6,5} = qubits {3,4,7,8}, pack bit 13 (q0) ===
    // j = pk<<13 | tid[8:7]<<11 | t[3]<<10 | t[2]<<9 | tid[6:5]<<7 | t[1]<<6 | t[0]<<5 | tid[4:0]
    {
        int a = (tid >> 7) * 2112 + ((tid >> 5) & 3) * 132 + (tid & 31);
#pragma unroll
        for (int t = 0; t < 16; t++) {
            int o = a + ((t >> 3) & 1) * 1056 + ((t >> 2) & 1) * 528
                      + ((t >> 1) & 1) * 66   + (t & 1) * 33;
            Ar[t] = pk2(RE[o], RE[o + 8448]);
            Ai[t] = pk2(IM[o], IM[o + 8448]);
        }
        { G g = mkg(cxv[8],  sxv[8]);  xx<8, 4>(Ar, Ai, g); } // XXb(3,4)
        { G g = mkg(cxv[10], sxv[10]); xx<2, 1>(Ar, Ai, g); } // XXb(7,8)
        { G g = mkg(c3[3], s3[3]); rx<8>(Ar, Ai, g); }
        { G g = mkg(c3[4], s3[4]); rx<4>(Ar, Ai, g); }
        { G g = mkg(c3[7], s3[7]); rx<2>(Ar, Ai, g); }
        { G g = mkg(c3[8], s3[8]); rx<1>(Ar, Ai, g); }
#pragma unroll
        for (int t = 0; t < 16; t++) {
            int o = a + ((t >> 3) & 1) * 1056 + ((t >> 2) & 1) * 528
                      + ((t >> 1) & 1) * 66   + (t & 1) * 33;
            float lo, hi;
            up2(Ar[t], lo, hi); RE[o] = lo; RE[o + 8448] = hi;
            up2(Ai[t], lo, hi); IM[o] = lo; IM[o + 8448] = hi;
        }
    }
    __syncthreads();

    // ====== P5: gate bits {13,2,1,0} = qubits {0,11,12,13}, pack bit 12 (q1) =
    // j = t[3]<<13 | pk<<12 | tid<<3 | t[2:0]
    {
        int a = tid * 8 + (tid >> 2);
#pragma unroll
        for (int t = 0; t < 16; t++) {
            int o = a + ((t >> 3) & 1) * 8448 + (t & 7);
            Ar[t] = pk2(RE[o], RE[o + 4224]);
            Ai[t] = pk2(IM[o], IM[o + 4224]);
        }
        { G g = mkg(cxv[6],  sxv[6]);  xx<2, 1>(Ar, Ai, g); } // XXa(12,13)
        { G g = mkg(czf[12], szf[12]); rz<2>(Ar, Ai, g); }
        { G g = mkg(czf[13], szf[13]); rz<1>(Ar, Ai, g); }
        { G g = mkg(cxv[12], sxv[12]); xx<4, 2>(Ar, Ai, g); } // XXb(11,12)
        { G g = mkg(cxv[13], sxv[13]); xx<1, 8>(Ar, Ai, g); } // XXb(13,0)
        { G g = mkg(c3[0],  s3[0]);  rx<8>(Ar, Ai, g); }
        { G g = mkg(c3[11], s3[11]); rx<4>(Ar, Ai, g); }
        { G g = mkg(c3[12], s3[12]); rx<2>(Ar, Ai, g); }
        { G g = mkg(c3[13], s3[13]); rx<1>(Ar, Ai, g); }

        // probabilities -> smem (reuse RE)
#pragma unroll
        for (int t = 0; t < 16; t++) {
            int o = a + ((t >> 3) & 1) * 8448 + (t & 7);
            u64 Pr = fma2(Ai[t], Ai[t], mul2(Ar[t], Ar[t]));
            float lo, hi; up2(Pr, lo, hi);
            RE[o] = lo; RE[o + 4224] = hi;
        }
    }
    __syncthreads();

    // ====== epilogue: inverse-permuted gather + 5-bit Walsh tree =============
    // y = new (post-permutation) index; prob_new[y] = prob_old[invperm(y)].
    // y = (k << 10) | (b9 << 9) | tid
    float l1[16], a4 = 0.0f;
#pragma unroll
    for (int k = 0; k < 16; k++) {
        int y0 = (k << 10) | tid;
        int y1 = y0 | 512;
        int x0 = d_permtab[y0];
        int x1 = d_permtab[y1];
        float v0 = RE[x0 + (x0 >> 5)];
        float v1 = RE[x1 + (x1 >> 5)];
        l1[k] = v0 + v1;
        a4 += v0 - v1;
    }
    float l2[8], a3 = 0.0f;
#pragma unroll
    for (int k = 0; k < 8; k++) { l2[k] = l1[2*k] + l1[2*k+1]; a3 += l1[2*k] - l1[2*k+1]; }
    float l3[4], a2 = 0.0f;
#pragma unroll
    for (int k = 0; k < 4; k++) { l3[k] = l2[2*k] + l2[2*k+1]; a2 += l2[2*k] - l2[2*k+1]; }
    float l4[2], a1 = 0.0f;
#pragma unroll
    for (int k = 0; k < 2; k++) { l4[k] = l3[2*k] + l3[2*k+1]; a1 += l3[2*k] - l3[2*k+1]; }
    float T  = l4[0] + l4[1];
    float a0 = l4[0] - l4[1];

    float aw[5] = {a0, a1, a2, a3, a4};
#pragma unroll
    for (int w = 0; w < NQ; w++) {
        float v = (w < 5) ? aw[w]
                          : (((tid >> (13 - w)) & 1) ? -T : T);
#pragma unroll
        for (int o = 16; o; o >>= 1) v += __shfl_xor_sync(0xffffffffu, v, o);
        if ((tid & 31) == 0) red[tid >> 5][w] = v;
    }
    __syncthreads();
    if (tid < NQ) {
        float v = 0.0f;
#pragma unroll
        for (int wp = 0; wp < 16; wp++) v += red[wp][tid];
        out[b * NQ + tid] = v;
    }
}

extern "C" void kernel_launch(void* const* d_in, const int* in_sizes, int n_in,
                              void* d_out, int out_size) {
    const float* cp = (const float*)d_in[0];   // (512, 14)
    const float* p  = (const float*)d_in[1];   // (512, 3, 14)
    float* out      = (float*)d_out;           // (512, 14)

    build_perm_kernel<<<NS / NTH, NTH>>>();

    size_t smem = (size_t)PAD_SLOTS * 2 * sizeof(float);  // 135168 bytes
    cudaFuncSetAttribute(quantum_kernel,
                         cudaFuncAttributeMaxDynamicSharedMemorySize, (int)smem);
    quantum_kernel<<<BATCH, NTH, smem>>>(cp, p, out);
}

// round 6
// speedup vs baseline: 2.7547x; 1.1444x over previous
#include <cuda_runtime.h>

#define NQ    14
#define NS    16384
#define NTH   512
#define BATCH 512
#define PAD_SLOTS (NS + (NS >> 5))   // 16896

typedef unsigned long long u64;

// ---------------- INVERSE MCX permutation table -----------------------------
__device__ unsigned short d_permtab[NS];

__global__ void build_perm_kernel() {
    int i = blockIdx.x * blockDim.x + threadIdx.x;
    unsigned x = (unsigned)i;
#pragma unroll
    for (int w = NQ - 1; w >= 0; w--) {
        const int p1 = NQ - 1 - w;
        const int p2 = NQ - 1 - ((w + 1) % NQ);
        const int pt = NQ - 1 - ((w + 2) % NQ);
        unsigned b1 = (x >> p1) & 1u;
        unsigned b2 = (x >> p2) & 1u;
        x ^= ((b1 & (b2 ^ 1u)) << pt);
    }
    d_permtab[i] = (unsigned short)x;
}

// ---------------- packed f32x2 primitives ------------------------------------
__device__ __forceinline__ u64 mul2(u64 a, u64 b) {
    u64 d; asm("mul.rn.f32x2 %0,%1,%2;" : "=l"(d) : "l"(a), "l"(b)); return d;
}
__device__ __forceinline__ u64 fma2(u64 a, u64 b, u64 c) {
    u64 d; asm("fma.rn.f32x2 %0,%1,%2,%3;" : "=l"(d) : "l"(a), "l"(b), "l"(c)); return d;
}
__device__ __forceinline__ u64 pk2(float lo, float hi) {
    u64 d; asm("mov.b64 %0,{%1,%2};" : "=l"(d) : "f"(lo), "f"(hi)); return d;
}
__device__ __forceinline__ void up2(u64 v, float& lo, float& hi) {
    asm("mov.b64 {%0,%1},%2;" : "=f"(lo), "=f"(hi) : "l"(v));
}

// fast-Givens gate constant: T = tan, Tn = -tan (cos deferred to phase kappa)
struct Gf { u64 T, Tn; };
__device__ __forceinline__ Gf mkgf(float t) {
    Gf g; g.T = pk2(t, t); g.Tn = pk2(-t, -t); return g;
}

// scaled mix: x' = x - i t y ; y' = y - i t x   (true result has extra *c)
__device__ __forceinline__ void mix2f(u64& Xr, u64& Xi, u64& Yr, u64& Yi, const Gf& g) {
    u64 xr = Xr, xi = Xi, yr = Yr, yi = Yi;
    Xr = fma2(g.T,  yi, xr);
    Xi = fma2(g.Tn, yr, xi);
    Yr = fma2(g.T,  xi, yr);
    Yi = fma2(g.Tn, xr, yi);
}

template <int MA, int MB>
__device__ __forceinline__ void xxf(u64* Ar, u64* Ai, const Gf& g) {
    const int M = MA | MB;
#pragma unroll
    for (int t = 0; t < 16; t++) {
        if (t & M) continue;
        mix2f(Ar[t],      Ai[t],      Ar[t ^ M],  Ai[t ^ M],  g);  // 00<->11
        mix2f(Ar[t | MA], Ai[t | MA], Ar[t | MB], Ai[t | MB], g);  // 10<->01
    }
}
template <int M>
__device__ __forceinline__ void rxf(u64* Ar, u64* Ai, const Gf& g) {
#pragma unroll
    for (int t = 0; t < 16; t++) {
        if (t & M) continue;
        mix2f(Ar[t], Ai[t], Ar[t | M], Ai[t | M], g);
    }
}
// symmetric Rz (scaled): bit0 *= (1 + i t) ; bit1 *= (1 - i t) ; true *= c each
template <int M>
__device__ __forceinline__ void rzf(u64* Ar, u64* Ai, const Gf& g) {
#pragma unroll
    for (int t = 0; t < 16; t++) {
        u64 r = Ar[t], i = Ai[t];
        if (t & M) {
            Ar[t] = fma2(g.Tn, i, r);
            Ai[t] = fma2(g.T,  r, i);
        } else {
            Ar[t] = fma2(g.T,  i, r);
            Ai[t] = fma2(g.Tn, r, i);
        }
    }
}
// rescale all 32 packed registers by phase kappa
__device__ __forceinline__ void scale32(u64* Ar, u64* Ai, float k) {
    u64 K = pk2(k, k);
#pragma unroll
    for (int t = 0; t < 16; t++) { Ar[t] = mul2(K, Ar[t]); Ai[t] = mul2(K, Ai[t]); }
}

// ---------------- main kernel ------------------------------------------------
__global__ void __launch_bounds__(NTH, 1)
quantum_kernel(const float* __restrict__ cp, const float* __restrict__ p,
               float* __restrict__ out) {
    extern __shared__ float sm[];
    float* RE = sm;
    float* IM = sm + PAD_SLOTS;

    __shared__ float c1[NQ], s1[NQ];   // Rx layer-1 half-angle (exact, for init)
    __shared__ float txv[NQ];          // tan(xx half): [0..6]=layer a, [7..13]=b
    __shared__ float t3[NQ];           // tan(rx3 half)
    __shared__ float tz[NQ];           // tan(rz half)
    __shared__ float cxc[NQ], c3c[NQ], czc[NQ];  // the deferred cosines
    __shared__ float kap[5];           // per-phase scale
    __shared__ float red[16][NQ];

    const int tid = threadIdx.x;
    const int b   = blockIdx.x;

    if (tid < NQ) {
        sincosf(0.5f * p[b * 3 * NQ + tid], &s1[tid], &c1[tid]);
    } else if (tid >= 32 && tid < 32 + NQ) {
        int w = tid - 32;
        float c, s; sincosf(0.5f * cp[b * NQ + w], &s, &c);
        txv[w] = __fdividef(s, c); cxc[w] = c;
    } else if (tid >= 64 && tid < 64 + NQ) {
        int w = tid - 64;
        float c, s; sincosf(0.5f * p[b * 3 * NQ + 2 * NQ + w], &s, &c);
        t3[w] = __fdividef(s, c); c3c[w] = c;
    } else if (tid >= 96 && tid < 96 + NQ) {
        int w = tid - 96;
        float c, s; sincosf(0.5f * p[b * 3 * NQ + NQ + w], &s, &c);
        tz[w] = __fdividef(s, c); czc[w] = c;
    }
    __syncthreads();

    // per-phase deferred-scale products (gate sets match phases below)
    if (tid == 0)
        kap[0] = cxc[0]*cxc[1]*czc[0]*czc[1]*czc[2]*czc[3]*cxc[7]*c3c[1]*c3c[2];
    else if (tid == 32)
        kap[1] = cxc[2]*cxc[3]*czc[4]*czc[5]*czc[6]*czc[7]*cxc[9]*c3c[5]*c3c[6];
    else if (tid == 64)
        kap[2] = cxc[4]*cxc[5]*czc[8]*czc[9]*czc[10]*czc[11]*cxc[11]*c3c[9]*c3c[10];
    else if (tid == 96)
        kap[3] = cxc[8]*cxc[10]*c3c[3]*c3c[4]*c3c[7]*c3c[8];
    else if (tid == 128)
        kap[4] = cxc[6]*czc[12]*czc[13]*cxc[12]*cxc[13]*c3c[0]*c3c[11]*c3c[12]*c3c[13];
    __syncthreads();

    u64 Ar[16], Ai[16];

    // ====== P1: gate bits {13,12,11,10} = qubits 0-3, pack bit 9 (qubit 4) ===
    // j = (t<<10) | (pk<<9) | tid
    {
        float pl = 1.0f;
#pragma unroll
        for (int bb = 0; bb < 9; bb++)
            pl *= ((tid >> bb) & 1) ? s1[13 - bb] : c1[13 - bb];
        int pc0 = __popc(tid);
        float f9c = c1[4], f9s = s1[4];
#pragma unroll
        for (int t = 0; t < 16; t++) {
            float Pb = pl;
#pragma unroll
            for (int k = 0; k < 4; k++)
                Pb *= ((t >> k) & 1) ? s1[3 - k] : c1[3 - k];
            int pcl = pc0 + __popc(t);
            float P0 = Pb * f9c;   int q0 = pcl & 3;
            float re0 = (q0 & 1) ? 0.0f : ((q0 & 2) ? -P0 : P0);
            float im0 = (q0 & 1) ? ((q0 == 1) ? -P0 : P0) : 0.0f;
            float P1v = Pb * f9s;  int q1 = (pcl + 1) & 3;
            float re1 = (q1 & 1) ? 0.0f : ((q1 & 2) ? -P1v : P1v);
            float im1 = (q1 & 1) ? ((q1 == 1) ? -P1v : P1v) : 0.0f;
            Ar[t] = pk2(re0, re1);
            Ai[t] = pk2(im0, im1);
        }
    }
    { Gf g = mkgf(txv[0]); xxf<8, 4>(Ar, Ai, g); }   // XXa(0,1)
    { Gf g = mkgf(txv[1]); xxf<2, 1>(Ar, Ai, g); }   // XXa(2,3)
    { Gf g = mkgf(tz[0]);  rzf<8>(Ar, Ai, g); }
    { Gf g = mkgf(tz[1]);  rzf<4>(Ar, Ai, g); }
    { Gf g = mkgf(tz[2]);  rzf<2>(Ar, Ai, g); }
    { Gf g = mkgf(tz[3]);  rzf<1>(Ar, Ai, g); }
    { Gf g = mkgf(txv[7]); xxf<4, 2>(Ar, Ai, g); }   // XXb(1,2)
    { Gf g = mkgf(t3[1]);  rxf<4>(Ar, Ai, g); }
    { Gf g = mkgf(t3[2]);  rxf<2>(Ar, Ai, g); }
    scale32(Ar, Ai, kap[0]);
    {
        int a = tid + (tid >> 5);
#pragma unroll
        for (int t = 0; t < 16; t++) {
            int o = a + t * 1056; float lo, hi;
            up2(Ar[t], lo, hi); RE[o] = lo; RE[o + 528] = hi;
            up2(Ai[t], lo, hi); IM[o] = lo; IM[o + 528] = hi;
        }
    }
    __syncthreads();

    // ====== P2: gate bits {9,8,7,6} = qubits 4-7, pack bit 5 (qubit 8) ======
    // j = (tid>>5)<<10 | t<<6 | pk<<5 | (tid&31)
    {
        int a = (tid >> 5) * 1056 + (tid & 31);
#pragma unroll
        for (int t = 0; t < 16; t++) {
            int o = a + t * 66;
            Ar[t] = pk2(RE[o], RE[o + 33]);
            Ai[t] = pk2(IM[o], IM[o + 33]);
        }
        { Gf g = mkgf(txv[2]); xxf<8, 4>(Ar, Ai, g); }   // XXa(4,5)
        { Gf g = mkgf(txv[3]); xxf<2, 1>(Ar, Ai, g); }   // XXa(6,7)
        { Gf g = mkgf(tz[4]);  rzf<8>(Ar, Ai, g); }
        { Gf g = mkgf(tz[5]);  rzf<4>(Ar, Ai, g); }
        { Gf g = mkgf(tz[6]);  rzf<2>(Ar, Ai, g); }
        { Gf g = mkgf(tz[7]);  rzf<1>(Ar, Ai, g); }
        { Gf g = mkgf(txv[9]); xxf<4, 2>(Ar, Ai, g); }   // XXb(5,6)
        { Gf g = mkgf(t3[5]);  rxf<4>(Ar, Ai, g); }
        { Gf g = mkgf(t3[6]);  rxf<2>(Ar, Ai, g); }
        scale32(Ar, Ai, kap[1]);
#pragma unroll
        for (int t = 0; t < 16; t++) {
            int o = a + t * 66; float lo, hi;
            up2(Ar[t], lo, hi); RE[o] = lo; RE[o + 33] = hi;
            up2(Ai[t], lo, hi); IM[o] = lo; IM[o + 33] = hi;
        }
    }
    __syncthreads();

    // ====== P3: gate bits {5,4,3,2} = qubits 8-11, pack bit 6 (qubit 7) =====
    // j = (tid>>2)<<7 | pk<<6 | t<<2 | (tid&3)
    {
        int a = (tid >> 2) * 132 + (tid & 3);
#pragma unroll
        for (int t = 0; t < 16; t++) {
            int o = a + t * 4 + (t >> 3);
            Ar[t] = pk2(RE[o], RE[o + 66]);
            Ai[t] = pk2(IM[o], IM[o + 66]);
        }
        { Gf g = mkgf(txv[4]);  xxf<8, 4>(Ar, Ai, g); }  // XXa(8,9)
        { Gf g = mkgf(txv[5]);  xxf<2, 1>(Ar, Ai, g); }  // XXa(10,11)
        { Gf g = mkgf(tz[8]);   rzf<8>(Ar, Ai, g); }
        { Gf g = mkgf(tz[9]);   rzf<4>(Ar, Ai, g); }
        { Gf g = mkgf(tz[10]);  rzf<2>(Ar, Ai, g); }
        { Gf g = mkgf(tz[11]);  rzf<1>(Ar, Ai, g); }
        { Gf g = mkgf(txv[11]); xxf<4, 2>(Ar, Ai, g); }  // XXb(9,10)
        { Gf g = mkgf(t3[9]);   rxf<4>(Ar, Ai, g); }
        { Gf g = mkgf(t3[10]);  rxf<2>(Ar, Ai, g); }
        scale32(Ar, Ai, kap[2]);
#pragma unroll
        for (int t = 0; t < 16; t++) {
            int o = a + t * 4 + (t >> 3); float lo, hi;
            up2(Ar[t], lo, hi); RE[o] = lo; RE[o + 66] = hi;
            up2(Ai[t], lo, hi); IM[o] = lo; IM[o + 66] = hi;
        }
    }
    __syncthreads();

    // ====== P4: gate bits {10,9,6,5} = qubits {3,4,7,8}, pack bit 13 (q0) ===
    {
        int a = (tid >> 7) * 2112 + ((tid >> 5) & 3) * 132 + (tid & 31);
#pragma unroll
        for (int t = 0; t < 16; t++) {
            int o = a + ((t >> 3) & 1) * 1056 + ((t >> 2) & 1) * 528
                      + ((t >> 1) & 1) * 66   + (t & 1) * 33;
            Ar[t] = pk2(RE[o], RE[o + 8448]);
            Ai[t] = pk2(IM[o], IM[o + 8448]);
        }
        { Gf g = mkgf(txv[8]);  xxf<8, 4>(Ar, Ai, g); }  // XXb(3,4)
        { Gf g = mkgf(txv[10]); xxf<2, 1>(Ar, Ai, g); }  // XXb(7,8)
        { Gf g = mkgf(t3[3]); rxf<8>(Ar, Ai, g); }
        { Gf g = mkgf(t3[4]); rxf<4>(Ar, Ai, g); }
        { Gf g = mkgf(t3[7]); rxf<2>(Ar, Ai, g); }
        { Gf g = mkgf(t3[8]); rxf<1>(Ar, Ai, g); }
        scale32(Ar, Ai, kap[3]);
#pragma unroll
        for (int t = 0; t < 16; t++) {
            int o = a + ((t >> 3) & 1) * 1056 + ((t >> 2) & 1) * 528
                      + ((t >> 1) & 1) * 66   + (t & 1) * 33;
            float lo, hi;
            up2(Ar[t], lo, hi); RE[o] = lo; RE[o + 8448] = hi;
            up2(Ai[t], lo, hi); IM[o] = lo; IM[o + 8448] = hi;
        }
    }
    __syncthreads();

    // ====== P5: gate bits {13,2,1,0} = qubits {0,11,12,13}, pack bit 12 (q1) =
    // (kappa[4] folded into the final output scalars)
    {
        int a = tid * 8 + (tid >> 2);
#pragma unroll
        for (int t = 0; t < 16; t++) {
            int o = a + ((t >> 3) & 1) * 8448 + (t & 7);
            Ar[t] = pk2(RE[o], RE[o + 4224]);
            Ai[t] = pk2(IM[o], IM[o + 4224]);
        }
        { Gf g = mkgf(txv[6]);  xxf<2, 1>(Ar, Ai, g); }  // XXa(12,13)
        { Gf g = mkgf(tz[12]);  rzf<2>(Ar, Ai, g); }
        { Gf g = mkgf(tz[13]);  rzf<1>(Ar, Ai, g); }
        { Gf g = mkgf(txv[12]); xxf<4, 2>(Ar, Ai, g); }  // XXb(11,12)
        { Gf g = mkgf(txv[13]); xxf<1, 8>(Ar, Ai, g); }  // XXb(13,0)
        { Gf g = mkgf(t3[0]);   rxf<8>(Ar, Ai, g); }
        { Gf g = mkgf(t3[11]);  rxf<4>(Ar, Ai, g); }
        { Gf g = mkgf(t3[12]);  rxf<2>(Ar, Ai, g); }
        { Gf g = mkgf(t3[13]);  rxf<1>(Ar, Ai, g); }

        // scaled probabilities -> smem (true prob = kap4^2 * value)
#pragma unroll
        for (int t = 0; t < 16; t++) {
            int o = a + ((t >> 3) & 1) * 8448 + (t & 7);
            u64 Pr = fma2(Ai[t], Ai[t], mul2(Ar[t], Ar[t]));
            float lo, hi; up2(Pr, lo, hi);
            RE[o] = lo; RE[o + 4224] = hi;
        }
    }
    __syncthreads();

    // ====== epilogue: inverse-permuted gather + 5-bit Walsh tree =============
    float l1[16], a4 = 0.0f;
#pragma unroll
    for (int k = 0; k < 16; k++) {
        int y0 = (k << 10) | tid;
        int y1 = y0 | 512;
        int x0 = d_permtab[y0];
        int x1 = d_permtab[y1];
        float v0 = RE[x0 + (x0 >> 5)];
        float v1 = RE[x1 + (x1 >> 5)];
        l1[k] = v0 + v1;
        a4 += v0 - v1;
    }
    float l2[8], a3 = 0.0f;
#pragma unroll
    for (int k = 0; k < 8; k++) { l2[k] = l1[2*k] + l1[2*k+1]; a3 += l1[2*k] - l1[2*k+1]; }
    float l3[4], a2 = 0.0f;
#pragma unroll
    for (int k = 0; k < 4; k++) { l3[k] = l2[2*k] + l2[2*k+1]; a2 += l2[2*k] - l2[2*k+1]; }
    float l4[2], a1 = 0.0f;
#pragma unroll
    for (int k = 0; k < 2; k++) { l4[k] = l3[2*k] + l3[2*k+1]; a1 += l3[2*k] - l3[2*k+1]; }
    float T  = l4[0] + l4[1];
    float a0 = l4[0] - l4[1];

    float aw[5] = {a0, a1, a2, a3, a4};
#pragma unroll
    for (int w = 0; w < NQ; w++) {
        float v = (w < 5) ? aw[w]
                          : (((tid >> (13 - w)) & 1) ? -T : T);
#pragma unroll
        for (int o = 16; o; o >>= 1) v += __shfl_xor_sync(0xffffffffu, v, o);
        if ((tid & 31) == 0) red[tid >> 5][w] = v;
    }
    __syncthreads();
    if (tid < NQ) {
        float v = 0.0f;
#pragma unroll
        for (int wp = 0; wp < 16; wp++) v += red[wp][tid];
        float k = kap[4];
        out[b * NQ + tid] = (v * k) * k;   // two-step to avoid k^2 underflow
    }
}

extern "C" void kernel_launch(void* const* d_in, const int* in_sizes, int n_in,
                              void* d_out, int out_size) {
    const float* cp = (const float*)d_in[0];   // (512, 14)
    const float* p  = (const float*)d_in[1];   // (512, 3, 14)
    float* out      = (float*)d_out;           // (512, 14)

    build_perm_kernel<<<NS / NTH, NTH>>>();

    size_t smem = (size_t)PAD_SLOTS * 2 * sizeof(float);  // 135168 bytes
    cudaFuncSetAttribute(quantum_kernel,
                         cudaFuncAttributeMaxDynamicSharedMemorySize, (int)smem);
    quantum_kernel<<<BATCH, NTH, smem>>>(cp, p, out);
}

// round 7
// speedup vs baseline: 2.8337x; 1.0287x over previous
#include <cuda_runtime.h>

#define NQ    14
#define NS    16384
#define NTH   512
#define BATCH 512
#define PAD_SLOTS (NS + (NS >> 5))   // 16896

typedef unsigned long long u64;

// ---------------- INVERSE MCX permutation table -----------------------------
__device__ unsigned short d_permtab[NS];

__global__ void build_perm_kernel() {
    int i = blockIdx.x * blockDim.x + threadIdx.x;
    unsigned x = (unsigned)i;
#pragma unroll
    for (int w = NQ - 1; w >= 0; w--) {
        const int p1 = NQ - 1 - w;
        const int p2 = NQ - 1 - ((w + 1) % NQ);
        const int pt = NQ - 1 - ((w + 2) % NQ);
        unsigned b1 = (x >> p1) & 1u;
        unsigned b2 = (x >> p2) & 1u;
        x ^= ((b1 & (b2 ^ 1u)) << pt);
    }
    d_permtab[i] = (unsigned short)x;
}

// ---------------- packed f32x2 primitives ------------------------------------
__device__ __forceinline__ u64 mul2(u64 a, u64 b) {
    u64 d; asm("mul.rn.f32x2 %0,%1,%2;" : "=l"(d) : "l"(a), "l"(b)); return d;
}
__device__ __forceinline__ u64 fma2(u64 a, u64 b, u64 c) {
    u64 d; asm("fma.rn.f32x2 %0,%1,%2,%3;" : "=l"(d) : "l"(a), "l"(b), "l"(c)); return d;
}
__device__ __forceinline__ u64 pk2(float lo, float hi) {
    u64 d; asm("mov.b64 %0,{%1,%2};" : "=l"(d) : "f"(lo), "f"(hi)); return d;
}
__device__ __forceinline__ void up2(u64 v, float& lo, float& hi) {
    asm("mov.b64 {%0,%1},%2;" : "=f"(lo), "=f"(hi) : "l"(v));
}

// fast-Givens gate constant: T = tan, Tn = -tan (cos deferred)
struct Gf { u64 T, Tn; };
__device__ __forceinline__ Gf mkgf(float t) {
    Gf g; g.T = pk2(t, t); g.Tn = pk2(-t, -t); return g;
}

// scaled mix: x' = x - i t y ; y' = y - i t x   (true result has extra *c)
__device__ __forceinline__ void mix2f(u64& Xr, u64& Xi, u64& Yr, u64& Yi, const Gf& g) {
    u64 xr = Xr, xi = Xi, yr = Yr, yi = Yi;
    Xr = fma2(g.T,  yi, xr);
    Xi = fma2(g.Tn, yr, xi);
    Yr = fma2(g.T,  xi, yr);
    Yi = fma2(g.Tn, xr, yi);
}

template <int MA, int MB>
__device__ __forceinline__ void xxf(u64* Ar, u64* Ai, const Gf& g) {
    const int M = MA | MB;
#pragma unroll
    for (int t = 0; t < 16; t++) {
        if (t & M) continue;
        mix2f(Ar[t],      Ai[t],      Ar[t ^ M],  Ai[t ^ M],  g);
        mix2f(Ar[t | MA], Ai[t | MA], Ar[t | MB], Ai[t | MB], g);
    }
}
template <int M>
__device__ __forceinline__ void rxf(u64* Ar, u64* Ai, const Gf& g) {
#pragma unroll
    for (int t = 0; t < 16; t++) {
        if (t & M) continue;
        mix2f(Ar[t], Ai[t], Ar[t | M], Ai[t | M], g);
    }
}
// symmetric Rz (scaled): bit=1 *= (1+it), bit=0 *= (1-it); true *= c each
template <int M>
__device__ __forceinline__ void rzf(u64* Ar, u64* Ai, const Gf& g) {
#pragma unroll
    for (int t = 0; t < 16; t++) {
        u64 r = Ar[t], i = Ai[t];
        if (t & M) {
            Ar[t] = fma2(g.Tn, i, r);
            Ai[t] = fma2(g.T,  r, i);
        } else {
            Ar[t] = fma2(g.T,  i, r);
            Ai[t] = fma2(g.Tn, r, i);
        }
    }
}
__device__ __forceinline__ void scale32(u64* Ar, u64* Ai, float k) {
    u64 K = pk2(k, k);
#pragma unroll
    for (int t = 0; t < 16; t++) { Ar[t] = mul2(K, Ar[t]); Ai[t] = mul2(K, Ai[t]); }
}

// (-i)^k rotation of a complex number
__device__ __forceinline__ void rot_mi(int k, float r, float i, float& orr, float& oi) {
    switch (k & 3) {
        case 0:  orr = r;  oi = i;  break;
        case 1:  orr = i;  oi = -r; break;
        case 2:  orr = -r; oi = -i; break;
        default: orr = -i; oi = r;  break;
    }
}

// one component of  Rz(wa)Rz(wb) * XX(phi) * (Rx|0> (x) Rx|0>)  on a wire pair
__device__ void pair_component(const float* p, const float* cp, int b,
                               int wa, int wb, int xxidx, int sel,
                               float& outr, float& outi) {
    float ca, sa, cbw, sbw, cx, sx;
    sincosf(0.5f * p[b * 42 + wa], &sa, &ca);
    sincosf(0.5f * p[b * 42 + wb], &sbw, &cbw);
    sincosf(0.5f * cp[b * 14 + xxidx], &sx, &cx);
    // (c,-is) (x) (c,-is):  v00=(cacb,0) v01=(0,-ca sb) v10=(0,-sa cb) v11=(-sa sb,0)
    float vr[4] = {ca * cbw, 0.0f, 0.0f, -sa * sbw};
    float vi[4] = {0.0f, -ca * sbw, -sa * cbw, 0.0f};
    float nr[4], ni[4];
    nr[0] = cx * vr[0] + sx * vi[3]; ni[0] = cx * vi[0] - sx * vr[3];
    nr[3] = cx * vr[3] + sx * vi[0]; ni[3] = cx * vi[3] - sx * vr[0];
    nr[1] = cx * vr[1] + sx * vi[2]; ni[1] = cx * vi[1] - sx * vr[2];
    nr[2] = cx * vr[2] + sx * vi[1]; ni[2] = cx * vi[2] - sx * vr[1];
    float tha = p[b * 42 + 14 + wa], thb = p[b * 42 + 14 + wb];
    float ph = 0.5f * (((sel >> 1) ? tha : -tha) + ((sel & 1) ? thb : -thb));
    float cph, sph; sincosf(ph, &sph, &cph);
    float ur = nr[sel], ui = ni[sel];
    outr = ur * cph - ui * sph;
    outi = ui * cph + ur * sph;
}

// ---------------- main kernel ------------------------------------------------
__global__ void __launch_bounds__(NTH, 1)
quantum_kernel(const float* __restrict__ cp, const float* __restrict__ p,
               float* __restrict__ out) {
    extern __shared__ float sm[];
    float* RE = sm;
    float* IM = sm + PAD_SLOTS;

    __shared__ float c1[NQ], s1[NQ];   // Rx layer-1 half-angle (wires 4-11 used)
    __shared__ float txv[NQ];          // tan(xx half): [0..6]=a, [7..13]=b
    __shared__ float t3[NQ];           // tan(rx3 half)
    __shared__ float tz[NQ];           // tan(rz half) (wires 4-11 used)
    __shared__ float cxc[NQ], c3c[NQ], czc[NQ];
    __shared__ float Vhr[16], Vhi2[16];  // fused wires 0-3 table
    __shared__ float chi_r[4], chi_i[4]; // fused wires 12,13 table
    __shared__ float kapA[3];          // {k1*k2, k3*k4, k5}
    __shared__ float red[16][12];

    const int tid = threadIdx.x;
    const int b   = blockIdx.x;

    // ---------------- setup stage 1 (disjoint thread ranges) ----------------
    if (tid < 16) {
        float w1r, w1i, w2r, w2i;
        pair_component(p, cp, b, 0, 1, 0, tid >> 2, w1r, w1i);
        pair_component(p, cp, b, 2, 3, 1, tid & 3,  w2r, w2i);
        Vhr[tid]  = w1r * w2r - w1i * w2i;
        Vhi2[tid] = w1r * w2i + w1i * w2r;
    }
    if (tid >= 16 && tid < 20) {
        float cr_, ci_;
        pair_component(p, cp, b, 12, 13, 6, tid - 16, cr_, ci_);
        chi_r[tid - 16] = cr_; chi_i[tid - 16] = ci_;
    }
    if (tid >= 32 && tid < 32 + NQ) {
        int w = tid - 32;
        float c, s; sincosf(0.5f * cp[b * NQ + w], &s, &c);
        txv[w] = __fdividef(s, c); cxc[w] = c;
    }
    if (tid >= 64 && tid < 64 + NQ) {
        int w = tid - 64;
        float c, s; sincosf(0.5f * p[b * 3 * NQ + 2 * NQ + w], &s, &c);
        t3[w] = __fdividef(s, c); c3c[w] = c;
    }
    if (tid >= 96 && tid < 96 + NQ) {
        int w = tid - 96;
        float c, s; sincosf(0.5f * p[b * 3 * NQ + NQ + w], &s, &c);
        tz[w] = __fdividef(s, c); czc[w] = c;
    }
    if (tid >= 128 && tid < 128 + NQ) {
        int w = tid - 128;
        sincosf(0.5f * p[b * 3 * NQ + w], &s1[w], &c1[w]);
    }
    __syncthreads();

    // ---------------- setup stage 2: deferred-scale products -----------------
    if (tid == 0)        // P1 (XXb(1,2),Rx3(1),Rx3(2)) * P2
        kapA[0] = cxc[7] * c3c[1] * c3c[2] *
                  cxc[2] * cxc[3] * czc[4] * czc[5] * czc[6] * czc[7] *
                  cxc[9] * c3c[5] * c3c[6];
    else if (tid == 32)  // P3 * P4
        kapA[1] = cxc[4] * cxc[5] * czc[8] * czc[9] * czc[10] * czc[11] *
                  cxc[11] * c3c[9] * c3c[10] *
                  cxc[8] * cxc[10] * c3c[3] * c3c[4] * c3c[7] * c3c[8];
    else if (tid == 64)  // P5 (XXb(11,12),XXb(13,0),Rx3 x4)
        kapA[2] = cxc[12] * cxc[13] * c3c[0] * c3c[11] * c3c[12] * c3c[13];
    __syncthreads();

    u64 Ar[16], Ai[16];

    // ====== P1: gate bits {13,12,11,10} = qubits 0-3, pack bit 9 (qubit 4) ===
    // init: Vhi (wires 0-3, fused XXa+Rz) * product(wires 4-11) * chi'(12,13)
    {
        float P = 1.0f;
#pragma unroll
        for (int bb = 2; bb <= 8; bb++)            // j bits 2..8 <-> wires 11..5
            P *= ((tid >> bb) & 1) ? s1[13 - bb] : c1[13 - bb];
        int pc = __popc(tid & 0x1FC);
        float Cr = chi_r[tid & 3], Ci = chi_i[tid & 3];
        float m0 = P * c1[4], m1 = P * s1[4];
        float R0r, R0i, R1r, R1i;
        rot_mi(pc,     Cr, Ci, R0r, R0i);
        rot_mi(pc + 1, Cr, Ci, R1r, R1i);
        float B0r = m0 * R0r, B0i = m0 * R0i;
        float B1r = m1 * R1r, B1i = m1 * R1i;
#pragma unroll
        for (int t = 0; t < 16; t++) {
            float vr = Vhr[t], vi = Vhi2[t];
            Ar[t] = pk2(vr * B0r - vi * B0i, vr * B1r - vi * B1i);
            Ai[t] = pk2(vr * B0i + vi * B0r, vr * B1i + vi * B1r);
        }
    }
    { Gf g = mkgf(txv[7]); xxf<4, 2>(Ar, Ai, g); }   // XXb(1,2)
    { Gf g = mkgf(t3[1]);  rxf<4>(Ar, Ai, g); }
    { Gf g = mkgf(t3[2]);  rxf<2>(Ar, Ai, g); }
    {
        int a = tid + (tid >> 5);
#pragma unroll
        for (int t = 0; t < 16; t++) {
            int o = a + t * 1056; float lo, hi;
            up2(Ar[t], lo, hi); RE[o] = lo; RE[o + 528] = hi;
            up2(Ai[t], lo, hi); IM[o] = lo; IM[o + 528] = hi;
        }
    }
    __syncthreads();

    // ====== P2: gate bits {9,8,7,6} = qubits 4-7, pack bit 5 (qubit 8) ======
    {
        int a = (tid >> 5) * 1056 + (tid & 31);
#pragma unroll
        for (int t = 0; t < 16; t++) {
            int o = a + t * 66;
            Ar[t] = pk2(RE[o], RE[o + 33]);
            Ai[t] = pk2(IM[o], IM[o + 33]);
        }
        { Gf g = mkgf(txv[2]); xxf<8, 4>(Ar, Ai, g); }   // XXa(4,5)
        { Gf g = mkgf(txv[3]); xxf<2, 1>(Ar, Ai, g); }   // XXa(6,7)
        { Gf g = mkgf(tz[4]);  rzf<8>(Ar, Ai, g); }
        { Gf g = mkgf(tz[5]);  rzf<4>(Ar, Ai, g); }
        { Gf g = mkgf(tz[6]);  rzf<2>(Ar, Ai, g); }
        { Gf g = mkgf(tz[7]);  rzf<1>(Ar, Ai, g); }
        { Gf g = mkgf(txv[9]); xxf<4, 2>(Ar, Ai, g); }   // XXb(5,6)
        { Gf g = mkgf(t3[5]);  rxf<4>(Ar, Ai, g); }
        { Gf g = mkgf(t3[6]);  rxf<2>(Ar, Ai, g); }
        scale32(Ar, Ai, kapA[0]);
#pragma unroll
        for (int t = 0; t < 16; t++) {
            int o = a + t * 66; float lo, hi;
            up2(Ar[t], lo, hi); RE[o] = lo; RE[o + 33] = hi;
            up2(Ai[t], lo, hi); IM[o] = lo; IM[o + 33] = hi;
        }
    }
    __syncthreads();

    // ====== P3: gate bits {5,4,3,2} = qubits 8-11, pack bit 6 (qubit 7) =====
    {
        int a = (tid >> 2) * 132 + (tid & 3);
#pragma unroll
        for (int t = 0; t < 16; t++) {
            int o = a + t * 4 + (t >> 3);
            Ar[t] = pk2(RE[o], RE[o + 66]);
            Ai[t] = pk2(IM[o], IM[o + 66]);
        }
        { Gf g = mkgf(txv[4]);  xxf<8, 4>(Ar, Ai, g); }  // XXa(8,9)
        { Gf g = mkgf(txv[5]);  xxf<2, 1>(Ar, Ai, g); }  // XXa(10,11)
        { Gf g = mkgf(tz[8]);   rzf<8>(Ar, Ai, g); }
        { Gf g = mkgf(tz[9]);   rzf<4>(Ar, Ai, g); }
        { Gf g = mkgf(tz[10]);  rzf<2>(Ar, Ai, g); }
        { Gf g = mkgf(tz[11]);  rzf<1>(Ar, Ai, g); }
        { Gf g = mkgf(txv[11]); xxf<4, 2>(Ar, Ai, g); }  // XXb(9,10)
        { Gf g = mkgf(t3[9]);   rxf<4>(Ar, Ai, g); }
        { Gf g = mkgf(t3[10]);  rxf<2>(Ar, Ai, g); }
#pragma unroll
        for (int t = 0; t < 16; t++) {
            int o = a + t * 4 + (t >> 3); float lo, hi;
            up2(Ar[t], lo, hi); RE[o] = lo; RE[o + 66] = hi;
            up2(Ai[t], lo, hi); IM[o] = lo; IM[o + 66] = hi;
        }
    }
    __syncthreads();

    // ====== P4: gate bits {10,9,6,5} = qubits {3,4,7,8}, pack bit 13 (q0) ===
    {
        int a = (tid >> 7) * 2112 + ((tid >> 5) & 3) * 132 + (tid & 31);
#pragma unroll
        for (int t = 0; t < 16; t++) {
            int o = a + ((t >> 3) & 1) * 1056 + ((t >> 2) & 1) * 528
                      + ((t >> 1) & 1) * 66   + (t & 1) * 33;
            Ar[t] = pk2(RE[o], RE[o + 8448]);
            Ai[t] = pk2(IM[o], IM[o + 8448]);
        }
        { Gf g = mkgf(txv[8]);  xxf<8, 4>(Ar, Ai, g); }  // XXb(3,4)
        { Gf g = mkgf(txv[10]); xxf<2, 1>(Ar, Ai, g); }  // XXb(7,8)
        { Gf g = mkgf(t3[3]); rxf<8>(Ar, Ai, g); }
        { Gf g = mkgf(t3[4]); rxf<4>(Ar, Ai, g); }
        { Gf g = mkgf(t3[7]); rxf<2>(Ar, Ai, g); }
        { Gf g = mkgf(t3[8]); rxf<1>(Ar, Ai, g); }
        scale32(Ar, Ai, kapA[1]);
#pragma unroll
        for (int t = 0; t < 16; t++) {
            int o = a + ((t >> 3) & 1) * 1056 + ((t >> 2) & 1) * 528
                      + ((t >> 1) & 1) * 66   + (t & 1) * 33;
            float lo, hi;
            up2(Ar[t], lo, hi); RE[o] = lo; RE[o + 8448] = hi;
            up2(Ai[t], lo, hi); IM[o] = lo; IM[o + 8448] = hi;
        }
    }
    __syncthreads();

    // ====== P5: gate bits {13,2,1,0} = qubits {0,11,12,13}, pack bit 12 =====
    // XXa(12,13), Rz(12), Rz(13) already folded into chi' at init.
    {
        int a = tid * 8 + (tid >> 2);
#pragma unroll
        for (int t = 0; t < 16; t++) {
            int o = a + ((t >> 3) & 1) * 8448 + (t & 7);
            Ar[t] = pk2(RE[o], RE[o + 4224]);
            Ai[t] = pk2(IM[o], IM[o + 4224]);
        }
        { Gf g = mkgf(txv[12]); xxf<4, 2>(Ar, Ai, g); }  // XXb(11,12)
        { Gf g = mkgf(txv[13]); xxf<1, 8>(Ar, Ai, g); }  // XXb(13,0)
        { Gf g = mkgf(t3[0]);   rxf<8>(Ar, Ai, g); }
        { Gf g = mkgf(t3[11]);  rxf<4>(Ar, Ai, g); }
        { Gf g = mkgf(t3[12]);  rxf<2>(Ar, Ai, g); }
        { Gf g = mkgf(t3[13]);  rxf<1>(Ar, Ai, g); }

        // scaled probabilities -> smem (true prob = kap5^2 * value)
#pragma unroll
        for (int t = 0; t < 16; t++) {
            int o = a + ((t >> 3) & 1) * 8448 + (t & 7);
            u64 Pr = fma2(Ai[t], Ai[t], mul2(Ar[t], Ar[t]));
            float lo, hi; up2(Pr, lo, hi);
            RE[o] = lo; RE[o + 4224] = hi;
        }
    }
    __syncthreads();

    // ====== epilogue: inverse-permuted gather + Walsh trees ==================
    float l1[16], a4 = 0.0f;
#pragma unroll
    for (int k = 0; k < 16; k++) {
        int y0 = (k << 10) | tid;
        int y1 = y0 | 512;
        int x0 = d_permtab[y0];
        int x1 = d_permtab[y1];
        float v0 = RE[x0 + (x0 >> 5)];
        float v1 = RE[x1 + (x1 >> 5)];
        l1[k] = v0 + v1;
        a4 += v0 - v1;
    }
    float l2[8], a3 = 0.0f;
#pragma unroll
    for (int k = 0; k < 8; k++) { l2[k] = l1[2*k] + l1[2*k+1]; a3 += l1[2*k] - l1[2*k+1]; }
    float l3[4], a2 = 0.0f;
#pragma unroll
    for (int k = 0; k < 4; k++) { l3[k] = l2[2*k] + l2[2*k+1]; a2 += l2[2*k] - l2[2*k+1]; }
    float l4[2], a1 = 0.0f;
#pragma unroll
    for (int k = 0; k < 2; k++) { l4[k] = l3[2*k] + l3[2*k+1]; a1 += l3[2*k] - l3[2*k+1]; }
    float T  = l4[0] + l4[1];
    float a0 = l4[0] - l4[1];

    // multi-accumulator warp butterfly:
    //   av[0..4] -> wires 0..4 ; d[k] -> wire 13-k ; T -> wires 5..8 via warp id
    float av[5] = {a0, a1, a2, a3, a4};
    float d[5];
#pragma unroll
    for (int k = 0; k < 5; k++) {
        float pT = __shfl_xor_sync(0xffffffffu, T, 1 << k);
        d[k] = T - pT;
        T += pT;
#pragma unroll
        for (int j = 0; j < 5; j++)
            av[j] += __shfl_xor_sync(0xffffffffu, av[j], 1 << k);
#pragma unroll
        for (int m = 0; m < 5; m++)
            if (m < k) d[m] += __shfl_xor_sync(0xffffffffu, d[m], 1 << k);
    }
    if ((tid & 31) == 0) {
        int wp = tid >> 5;
#pragma unroll
        for (int j = 0; j < 5; j++) red[wp][j] = av[j];
#pragma unroll
        for (int k = 0; k < 5; k++) red[wp][5 + k] = d[k];
        red[wp][10] = T;
    }
    __syncthreads();
    if (tid < NQ) {
        float v = 0.0f;
        if (tid < 5) {
#pragma unroll
            for (int wp = 0; wp < 16; wp++) v += red[wp][tid];
        } else if (tid < 9) {
#pragma unroll
            for (int wp = 0; wp < 16; wp++)
                v += ((wp >> (8 - tid)) & 1) ? -red[wp][10] : red[wp][10];
        } else {
#pragma unroll
            for (int wp = 0; wp < 16; wp++) v += red[wp][5 + 13 - tid];
        }
        float k5 = kapA[2];
        out[b * NQ + tid] = (v * k5) * k5;
    }
}

extern "C" void kernel_launch(void* const* d_in, const int* in_sizes, int n_in,
                              void* d_out, int out_size) {
    const float* cp = (const float*)d_in[0];   // (512, 14)
    const float* p  = (const float*)d_in[1];   // (512, 3, 14)
    float* out      = (float*)d_out;           // (512, 14)

    build_perm_kernel<<<NS / NTH, NTH>>>();

    size_t smem = (size_t)PAD_SLOTS * 2 * sizeof(float);  // 135168 bytes
    cudaFuncSetAttribute(quantum_kernel,
                         cudaFuncAttributeMaxDynamicSharedMemorySize, (int)smem);
    quantum_kernel<<<BATCH, NTH, smem>>>(cp, p, out);
}